// round 6
// baseline (speedup 1.0000x reference)
#include <cuda_runtime.h>
#include <cuda_fp16.h>
#include <cstdint>

#define B_   8
#define T_   16
#define H_   64
#define W_   64
#define CIN  32
#define F_   64
#define NC   256          // 4*F gates [i,f,c,o]
#define NSL  14           // 5 x-slices (K=64, k9 pairs) + 9 h-slices (K=64)

#define PITCH     72                   // halfs per smem row (144 B)
#define A_HALFS   (64 * PITCH)         // 4608
#define BUF_HALFS (A_HALFS + 256 * PITCH)   // 23040 halfs = 46080 B
#define SMEMB     (2 * BUF_HALFS * 2)       // 92160 B (double buffer)

// Persistent state. h in fp16 (feeds fp16 MMA), c in fp32.
__device__ __half g_hh[2][B_ * H_ * W_ * F_];
__device__ float  g_c[B_ * H_ * W_ * F_];
// x pre-converted to fp16 (same rn conversion as R5's staging path)
__device__ __half g_xh[B_ * T_ * H_ * W_ * CIN];
// Pre-packed fp16 weights: [slice][nSm][64]  (gate-permuted cols, K-major)
__device__ __half g_w2[NSL][256][64];

__device__ __forceinline__ float hsig(float x) {
    return __saturatef((x + 3.0f) * 0.16666667f);  // hard_sigmoid
}
__device__ __forceinline__ uint32_t smem_u32(const void* p) {
    uint32_t a;
    asm("{ .reg .u64 t; cvta.to.shared.u64 t, %1; cvt.u32.u64 %0, t; }"
        : "=r"(a) : "l"(p));
    return a;
}
__device__ __forceinline__ uint64_t gaddr(const void* p) {
    uint64_t a;
    asm("cvta.to.global.u64 %0, %1;" : "=l"(a) : "l"(p));
    return a;
}

#define CP16(dst, src, sz) \
    asm volatile("cp.async.ca.shared.global [%0], [%1], 16, %2;" \
                 :: "r"(dst), "l"(src), "r"(sz) : "memory")
#define CP_COMMIT() asm volatile("cp.async.commit_group;" ::: "memory")
#define CP_WAIT1()  asm volatile("cp.async.wait_group 1;" ::: "memory")
#define CP_WAIT0()  asm volatile("cp.async.wait_group 0;" ::: "memory")

#define LDSM4(r0, r1, r2, r3, addr) \
    asm volatile("ldmatrix.sync.aligned.m8n8.x4.shared.b16 {%0,%1,%2,%3}, [%4];" \
        : "=r"(r0), "=r"(r1), "=r"(r2), "=r"(r3) : "r"(addr))

#define MMA16816(d, a0, a1, a2, a3, b0, b1) \
    asm volatile("mma.sync.aligned.m16n8k16.row.col.f32.f16.f16.f32 " \
        "{%0,%1,%2,%3}, {%4,%5,%6,%7}, {%8,%9}, {%0,%1,%2,%3};" \
        : "+f"((d)[0]), "+f"((d)[1]), "+f"((d)[2]), "+f"((d)[3]) \
        : "r"(a0), "r"(a1), "r"(a2), "r"(a3), "r"(b0), "r"(b1))

// ---- one-time preps (in graph; cheap & deterministic) ----
__global__ void prep_x(const float* __restrict__ x) {
    size_t i = ((size_t)blockIdx.x * 256 + threadIdx.x) * 4;
    float4 v = *(const float4*)(x + i);
    __half2 h2[2];
    h2[0] = __floats2half2_rn(v.x, v.y);
    h2[1] = __floats2half2_rn(v.z, v.w);
    *(uint2*)&g_xh[i] = *(uint2*)h2;
}

__global__ void prep_w(const float* __restrict__ Wt,
                       const float* __restrict__ Ut) {
    const int s = blockIdx.x;       // 0..13
    const int n = threadIdx.x;      // nSm = warp_n*64 + g*16 + fi
    const int g = (n >> 4) & 3;
    const int f = (n >> 6) * 16 + (n & 15);
    const int j = g * 64 + f;       // source output-column
    __half* dst = g_w2[s][n];
    if (s < 5) {
        #pragma unroll
        for (int hh = 0; hh < 2; ++hh) {
            const int k9 = 2 * s + hh;
            for (int k = 0; k < 32; ++k)
                dst[hh * 32 + k] = (k9 < 9)
                    ? __float2half_rn(Wt[((size_t)k9 * CIN + k) * NC + j])
                    : __float2half_rn(0.f);
        }
    } else {
        const int k9 = s - 5;
        for (int k = 0; k < 64; ++k)
            dst[k] = __float2half_rn(Ut[((size_t)k9 * F_ + k) * NC + j]);
    }
}

// Prefetch one K=64 slice into buffer (cp.async, 10x16B per thread).
__device__ __forceinline__ void prefetch_slice(
    int s, uint32_t bufA, uint32_t bufB, int tid,
    const __half* xframe, const __half* hframe, int y0, int x0)
{
    // ---- B: row n = tid, 128 B ----
    {
        uint64_t src = gaddr(g_w2[s][tid]);
        uint32_t dst = bufB + (uint32_t)tid * 144u;
        #pragma unroll
        for (int j = 0; j < 8; ++j) CP16(dst + j * 16, src + j * 16, 16);
    }
    // ---- A: row = tid>>2 (pixel), q = tid&3 (16B chunk in each half) ----
    const int row = tid >> 2, q = tid & 3;
    const int apy = row >> 3, apx = row & 7;
    const uint32_t adst = bufA + (uint32_t)row * 144u + q * 16;
    int k9a, k9b, c0b, strideC;
    const __half* src;
    if (s < 5) { k9a = 2 * s; k9b = 2 * s + 1; src = xframe; c0b = 0; strideC = CIN; }
    else       { k9a = s - 5; k9b = s - 5;     src = hframe; c0b = 32; strideC = F_; }
    {   // half 0
        const int ky = k9a / 3, kx = k9a - 3 * (k9a / 3);
        const int gy = y0 + apy + ky - 1, gx = x0 + apx + kx - 1;
        const bool ok = (unsigned)gy < H_ && (unsigned)gx < W_;
        const __half* p = src + (ok ? ((size_t)gy * W_ + gx) * strideC : 0) + q * 8;
        CP16(adst, gaddr(p), ok ? 16 : 0);
    }
    {   // half 1
        const int ky = k9b / 3, kx = k9b - 3 * (k9b / 3);
        const int gy = y0 + apy + ky - 1, gx = x0 + apx + kx - 1;
        const bool ok = (k9b < 9) && (unsigned)gy < H_ && (unsigned)gx < W_;
        const __half* p = src + (ok ? ((size_t)gy * W_ + gx) * strideC + c0b : 0) + q * 8;
        CP16(adst + 64, gaddr(p), ok ? 16 : 0);
    }
}

// One ConvLSTM timestep: HMMA implicit GEMM, double-buffered cp.async pipeline.
// CTA: 8x8 pixels (M=64) x N=256. 8 warps (2m x 4n), warp tile 32x64.
template<bool FIRST>
__global__ __launch_bounds__(256, 2)
void step_mma(const float* __restrict__ bias, int t, int hsel,
              float* __restrict__ out, int last)
{
    extern __shared__ __half sm[];
    const int tid  = threadIdx.x;
    const int lane = tid & 31;
    const int w    = tid >> 5;
    const int warp_m = w & 1;
    const int warp_n = w >> 1;
    const int b  = blockIdx.z;
    const int y0 = blockIdx.y * 8;
    const int x0 = blockIdx.x * 8;

    const __half* xframe = g_xh + (size_t)(b * T_ + t) * H_ * W_ * CIN;
    const __half* hframe = g_hh[hsel] + (size_t)b * H_ * W_ * F_;

    const uint32_t sb = smem_u32(sm);
    const uint32_t bufA[2] = { sb, sb + BUF_HALFS * 2 };
    const uint32_t bufB[2] = { sb + A_HALFS * 2, sb + BUF_HALFS * 2 + A_HALFS * 2 };

    float d[2][8][4];
    #pragma unroll
    for (int mt = 0; mt < 2; ++mt)
        #pragma unroll
        for (int nt = 0; nt < 8; ++nt)
            #pragma unroll
            for (int c = 0; c < 4; ++c) d[mt][nt][c] = 0.f;

    const int NS = FIRST ? 5 : NSL;
    prefetch_slice(0, bufA[0], bufB[0], tid, xframe, hframe, y0, x0);
    CP_COMMIT();

    for (int s = 0; s < NS; ++s) {
        if (s + 1 < NS) {
            prefetch_slice(s + 1, bufA[(s + 1) & 1], bufB[(s + 1) & 1], tid,
                           xframe, hframe, y0, x0);
            CP_COMMIT();
            CP_WAIT1();
        } else {
            CP_WAIT0();
        }
        __syncthreads();            // buffer s&1 visible to all

        const uint32_t aA = bufA[s & 1];
        const uint32_t aB = bufB[s & 1];
        #pragma unroll
        for (int kk = 0; kk < 4; ++kk) {
            uint32_t a[2][4];
            #pragma unroll
            for (int mt = 0; mt < 2; ++mt) {
                uint32_t ad = aA
                    + (uint32_t)(warp_m * 32 + mt * 16 + (lane & 15)) * 144u
                    + (uint32_t)(kk * 32 + ((lane >> 4) << 4));
                LDSM4(a[mt][0], a[mt][1], a[mt][2], a[mt][3], ad);
            }
            #pragma unroll
            for (int p = 0; p < 4; ++p) {
                uint32_t n = (uint32_t)(warp_n * 64 + p * 16
                                        + ((lane >> 4) << 3) + (lane & 7));
                uint32_t bd = aB + n * 144u
                    + (uint32_t)(kk * 32 + (((lane >> 3) & 1) << 4));
                uint32_t b0, b1, b2, b3;
                LDSM4(b0, b1, b2, b3, bd);
                MMA16816(d[0][2 * p + 0], a[0][0], a[0][1], a[0][2], a[0][3], b0, b1);
                MMA16816(d[0][2 * p + 1], a[0][0], a[0][1], a[0][2], a[0][3], b2, b3);
                MMA16816(d[1][2 * p + 0], a[1][0], a[1][1], a[1][2], a[1][3], b0, b1);
                MMA16816(d[1][2 * p + 1], a[1][0], a[1][1], a[1][2], a[1][3], b2, b3);
            }
        }
        __syncthreads();            // all reads done before s+2 overwrites
    }

    // ================= fused LSTM epilogue (layout as R5, verified) =======
    __half* hhout = g_hh[hsel ^ 1];
    const int fq = 2 * (lane & 3);

    #pragma unroll
    for (int mt = 0; mt < 2; ++mt) {
        #pragma unroll
        for (int rh = 0; rh < 2; ++rh) {
            const int m  = warp_m * 32 + mt * 16 + rh * 8 + (lane >> 2);
            const int py = m >> 3, px = m & 7;
            const size_t pix =
                (((size_t)b * H_ + (y0 + py)) * W_ + (x0 + px)) * F_;
            #pragma unroll
            for (int t1 = 0; t1 < 2; ++t1) {
                const int f0 = warp_n * 16 + t1 * 8 + fq;
                float zi0 = d[mt][0 + t1][rh * 2 + 0], zi1 = d[mt][0 + t1][rh * 2 + 1];
                float zf0 = d[mt][2 + t1][rh * 2 + 0], zf1 = d[mt][2 + t1][rh * 2 + 1];
                float zc0 = d[mt][4 + t1][rh * 2 + 0], zc1 = d[mt][4 + t1][rh * 2 + 1];
                float zo0 = d[mt][6 + t1][rh * 2 + 0], zo1 = d[mt][6 + t1][rh * 2 + 1];

                float2 co = make_float2(0.f, 0.f);
                if (!FIRST) co = *(const float2*)&g_c[pix + f0];

                float ig0 = hsig(zi0 + bias[f0]);
                float fg0 = hsig(zf0 + bias[64 + f0]);
                float zz0 =      zc0 + bias[128 + f0];
                float og0 = hsig(zo0 + bias[192 + f0]);
                float cn0 = fg0 * co.x + ig0 * fmaxf(zz0, 0.f);
                float hn0 = og0 * fmaxf(cn0, 0.f);

                float ig1 = hsig(zi1 + bias[f0 + 1]);
                float fg1 = hsig(zf1 + bias[65 + f0]);
                float zz1 =      zc1 + bias[129 + f0];
                float og1 = hsig(zo1 + bias[193 + f0]);
                float cn1 = fg1 * co.y + ig1 * fmaxf(zz1, 0.f);
                float hn1 = og1 * fmaxf(cn1, 0.f);

                if (!last) {
                    *(float2*)&g_c[pix + f0] = make_float2(cn0, cn1);
                    *(__half2*)&hhout[pix + f0] = __floats2half2_rn(hn0, hn1);
                } else {
                    *(float2*)&out[pix + f0] = make_float2(hn0, hn1);
                }
            }
        }
    }
}

extern "C" void kernel_launch(void* const* d_in, const int* in_sizes, int n_in,
                              void* d_out, int out_size)
{
    const float* x = nullptr; const float* Wt = nullptr;
    const float* Ut = nullptr; const float* bias = nullptr;
    for (int i = 0; i < n_in; ++i) {
        switch (in_sizes[i]) {
            case B_*T_*H_*W_*CIN: x    = (const float*)d_in[i]; break;
            case 3*3*CIN*NC:      Wt   = (const float*)d_in[i]; break;
            case 3*3*F_*NC:       Ut   = (const float*)d_in[i]; break;
            case NC:              bias = (const float*)d_in[i]; break;
        }
    }
    if (!x || !Wt || !Ut || !bias) {
        x = (const float*)d_in[0]; Wt = (const float*)d_in[1];
        Ut = (const float*)d_in[2]; bias = (const float*)d_in[3];
    }
    float* out = (float*)d_out;

    prep_x<<<(B_ * T_ * H_ * W_ * CIN) / 1024, 256>>>(x);
    prep_w<<<NSL, 256>>>(Wt, Ut);

    cudaFuncSetAttribute(step_mma<true>,
                         cudaFuncAttributeMaxDynamicSharedMemorySize, SMEMB);
    cudaFuncSetAttribute(step_mma<false>,
                         cudaFuncAttributeMaxDynamicSharedMemorySize, SMEMB);

    dim3 grid(W_ / 8, H_ / 8, B_);    // 512 CTAs
    dim3 block(256);

    step_mma<true><<<grid, block, SMEMB>>>(bias, 0, 0, out, 0);
    for (int t = 1; t < T_; ++t) {
        int last = (t == T_ - 1);
        step_mma<false><<<grid, block, SMEMB>>>(bias, t, t & 1, out, last);
    }
}

// round 7
// speedup vs baseline: 2.7513x; 2.7513x over previous
#include <cuda_runtime.h>
#include <cuda_fp16.h>
#include <cstdint>

#define B_   8
#define T_   16
#define H_   64
#define W_   64
#define CIN  32
#define F_   64
#define NC   256          // 4*F gates [i,f,c,o]
#define NSL  27           // 9 x-slices + 18 h-slices (K=32 each)

// Persistent state. h in fp16 (feeds fp16 MMA), c in fp32.
__device__ __half g_hh[2][B_ * H_ * W_ * F_];
__device__ float  g_c[B_ * H_ * W_ * F_];
// x pre-converted to fp16
__device__ __half g_xh[B_ * T_ * H_ * W_ * CIN];
// Weights pre-packed in MMA B-fragment order:
// [slice][warp_n][idx = kk*4+p][lane] -> uint4 (= regs b0,b1,b2,b3 of R5's LDSM4)
__device__ uint4 g_bf[NSL][4][8][32];

#define XH_PITCH 80     // bytes per halo pixel row (x: 64B data + pad)
#define HH_PITCH 144    // bytes per halo pixel row (h: 128B data + pad)
#define SM_XH 0
#define SM_HH 8000      // 100*80
#define SM_TOT (8000 + 100 * 144)   // 22400 B

__device__ __forceinline__ float hsig(float x) {
    return __saturatef((x + 3.0f) * 0.16666667f);  // hard_sigmoid
}
__device__ __forceinline__ uint32_t smem_u32(const void* p) {
    uint32_t a;
    asm("{ .reg .u64 t; cvta.to.shared.u64 t, %1; cvt.u32.u64 %0, t; }"
        : "=r"(a) : "l"(p));
    return a;
}

#define LDSM4(r0, r1, r2, r3, addr) \
    asm volatile("ldmatrix.sync.aligned.m8n8.x4.shared.b16 {%0,%1,%2,%3}, [%4];" \
        : "=r"(r0), "=r"(r1), "=r"(r2), "=r"(r3) : "r"(addr))

#define MMA16816(d, a0, a1, a2, a3, b0, b1) \
    asm volatile("mma.sync.aligned.m16n8k16.row.col.f32.f16.f16.f32 " \
        "{%0,%1,%2,%3}, {%4,%5,%6,%7}, {%8,%9}, {%0,%1,%2,%3};" \
        : "+f"((d)[0]), "+f"((d)[1]), "+f"((d)[2]), "+f"((d)[3]) \
        : "r"(a0), "r"(a1), "r"(a2), "r"(a3), "r"(b0), "r"(b1))

// ---- one-time preps ----
__global__ void prep_x(const float* __restrict__ x) {
    size_t i = ((size_t)blockIdx.x * 256 + threadIdx.x) * 4;
    float4 v = *(const float4*)(x + i);
    __half2 h2[2];
    h2[0] = __floats2half2_rn(v.x, v.y);
    h2[1] = __floats2half2_rn(v.z, v.w);
    *(uint2*)&g_xh[i] = *(uint2*)h2;
}

// Pack weights into B-fragment order. Reproduces exactly what R5's
// ldmatrix.x4 delivered: reg jm of lane l = halfs kb,kb+1 of permuted col
// n(a), a = 8*jm + (l>>2), kb = kk*16 + ((a>>3)&1)*8 + 2*(l&3).
__global__ void prep_bf(const float* __restrict__ Wt,
                        const float* __restrict__ Ut) {
    const int s    = blockIdx.x;          // 0..26
    const int wn   = blockIdx.y;          // 0..3
    const int idx  = threadIdx.x >> 5;    // 0..7
    const int lane = threadIdx.x & 31;
    const int kk = idx >> 2, p = idx & 3;

    uint32_t r[4];
    #pragma unroll
    for (int jm = 0; jm < 4; ++jm) {
        const int a  = 8 * jm + (lane >> 2);
        const int n  = wn * 64 + p * 16 + ((a >> 4) << 3) + (a & 7);
        const int jcol = ((n >> 4) & 3) * 64 + (n >> 6) * 16 + (n & 15);
        const int kb = kk * 16 + ((a >> 3) & 1) * 8 + 2 * (lane & 3);
        float w0, w1;
        if (s < 9) {
            const float* bp = Wt + ((size_t)s * CIN + kb) * NC + jcol;
            w0 = bp[0]; w1 = bp[NC];
        } else {
            const int u = s - 9, k9 = u >> 1, c0 = (u & 1) * 32;
            const float* bp = Ut + ((size_t)k9 * F_ + c0 + kb) * NC + jcol;
            w0 = bp[0]; w1 = bp[NC];
        }
        __half2 h2 = __floats2half2_rn(w0, w1);
        r[jm] = *(uint32_t*)&h2;
    }
    g_bf[s][wn][idx][lane] = make_uint4(r[0], r[1], r[2], r[3]);
}

// One ConvLSTM timestep. CTA: 8x8 pixels (M=64) x N=256, 8 warps (2m x 4n).
// Persistent halos in smem; zero barriers in mainloop; B frags via LDG
// with distance-2 register prefetch.
template<bool FIRST>
__global__ __launch_bounds__(256, 2)
void step_mma(const float* __restrict__ bias, int t, int hsel,
              float* __restrict__ out, int last)
{
    __shared__ __align__(16) char sm[SM_TOT];

    const int tid  = threadIdx.x;
    const int lane = tid & 31;
    const int w    = tid >> 5;
    const int warp_m = w & 1;
    const int warp_n = w >> 1;
    const int b  = blockIdx.z;
    const int y0 = blockIdx.y * 8;
    const int x0 = blockIdx.x * 8;

    const __half* xframe = g_xh + (size_t)(b * T_ + t) * H_ * W_ * CIN;
    const __half* hframe = g_hh[hsel] + (size_t)b * H_ * W_ * F_;

    // ---- stage halos once ----
    for (int j = tid; j < 400; j += 256) {            // x: 100 px * 4 chunks
        const int p = j >> 2, q = j & 3;
        const int gy = y0 + p / 10 - 1, gx = x0 + p % 10 - 1;
        uint4 v = make_uint4(0u, 0u, 0u, 0u);
        if ((unsigned)gy < H_ && (unsigned)gx < W_)
            v = *(const uint4*)(xframe + ((size_t)gy * W_ + gx) * CIN + q * 8);
        *(uint4*)(sm + SM_XH + p * XH_PITCH + q * 16) = v;
    }
    if (!FIRST) {
        for (int j = tid; j < 800; j += 256) {        // h: 100 px * 8 chunks
            const int p = j >> 3, q = j & 7;
            const int gy = y0 + p / 10 - 1, gx = x0 + p % 10 - 1;
            uint4 v = make_uint4(0u, 0u, 0u, 0u);
            if ((unsigned)gy < H_ && (unsigned)gx < W_)
                v = *(const uint4*)(hframe + ((size_t)gy * W_ + gx) * F_ + q * 8);
            *(uint4*)(sm + SM_HH + p * HH_PITCH + q * 16) = v;
        }
    }
    __syncthreads();   // the only barrier before the epilogue

    // ---- per-lane A ldmatrix base addresses ----
    const uint32_t sb = smem_u32(sm);
    const int hi  = (lane >> 4) << 4;
    const int m0  = warp_m * 32 + (lane & 15);
    const int m1  = m0 + 16;
    const int f0p = (m0 >> 3) * 10 + (m0 & 7);
    const int f1p = (m1 >> 3) * 10 + (m1 & 7);
    const uint32_t aAx0 = sb + SM_XH + f0p * XH_PITCH + hi;
    const uint32_t aAx1 = sb + SM_XH + f1p * XH_PITCH + hi;
    const uint32_t aAh0 = sb + SM_HH + f0p * HH_PITCH + hi;
    const uint32_t aAh1 = sb + SM_HH + f1p * HH_PITCH + hi;

    float d[2][8][4];
    #pragma unroll
    for (int mt = 0; mt < 2; ++mt)
        #pragma unroll
        for (int nt = 0; nt < 8; ++nt)
            #pragma unroll
            for (int c = 0; c < 4; ++c) d[mt][nt][c] = 0.f;

    const int NS = FIRST ? 9 : NSL;
    // B fragment pointers (uint4 units; group idx stride = 32 uint4 = 512B)
    const uint4* bp = &g_bf[0][warp_n][0][lane];
    uint4 bb[4];
    bb[0] = bp[0];
    bb[1] = bp[32];

    #define SLICE_BODY(A0, A1, SOFF)                                          \
    do {                                                                      \
        const uint4* bnp = bp + ((s + 1 < NS) ? (4 * 8 * 32) : 0);            \
        _Pragma("unroll")                                                     \
        for (int kk = 0; kk < 2; ++kk) {                                      \
            uint32_t a0r[4], a1r[4];                                          \
            LDSM4(a0r[0], a0r[1], a0r[2], a0r[3], (A0) + (SOFF) + kk * 32);   \
            LDSM4(a1r[0], a1r[1], a1r[2], a1r[3], (A1) + (SOFF) + kk * 32);   \
            _Pragma("unroll")                                                 \
            for (int p = 0; p < 4; ++p) {                                     \
                const int idx = kk * 4 + p;                                   \
                const uint4* pf = (idx + 2 < 8) ? (bp + (idx + 2) * 32)       \
                                                : (bnp + (idx - 6) * 32);     \
                uint4 nb = *pf;                                               \
                uint4 cb = bb[p];                                             \
                MMA16816(d[0][2 * p + 0], a0r[0], a0r[1], a0r[2], a0r[3], cb.x, cb.y); \
                MMA16816(d[0][2 * p + 1], a0r[0], a0r[1], a0r[2], a0r[3], cb.z, cb.w); \
                MMA16816(d[1][2 * p + 0], a1r[0], a1r[1], a1r[2], a1r[3], cb.x, cb.y); \
                MMA16816(d[1][2 * p + 1], a1r[0], a1r[1], a1r[2], a1r[3], cb.z, cb.w); \
                bb[(p + 2) & 3] = nb;                                         \
            }                                                                 \
        }                                                                     \
        bp = bnp;                                                             \
    } while (0)

    // x-conv slices
    for (int s = 0; s < 9; ++s) {
        const int ky = s / 3, kx = s - 3 * (s / 3);
        const uint32_t soff = (uint32_t)(ky * 10 + kx) * XH_PITCH;
        SLICE_BODY(aAx0, aAx1, soff);
    }
    // h-conv slices
    if (!FIRST) {
        for (int s = 9; s < NSL; ++s) {
            const int u = s - 9, k9 = u >> 1, c0 = (u & 1) * 32;
            const int ky = k9 / 3, kx = k9 - 3 * (k9 / 3);
            const uint32_t soff = (uint32_t)(ky * 10 + kx) * HH_PITCH + c0 * 2;
            SLICE_BODY(aAh0, aAh1, soff);
        }
    }
    #undef SLICE_BODY

    // ================= fused LSTM epilogue (R5-verified layout) ===========
    __half* hhout = g_hh[hsel ^ 1];
    const int fq = 2 * (lane & 3);

    #pragma unroll
    for (int mt = 0; mt < 2; ++mt) {
        #pragma unroll
        for (int rh = 0; rh < 2; ++rh) {
            const int m  = warp_m * 32 + mt * 16 + rh * 8 + (lane >> 2);
            const int py = m >> 3, px = m & 7;
            const size_t pix =
                (((size_t)b * H_ + (y0 + py)) * W_ + (x0 + px)) * F_;
            #pragma unroll
            for (int t1 = 0; t1 < 2; ++t1) {
                const int f0 = warp_n * 16 + t1 * 8 + fq;
                float zi0 = d[mt][0 + t1][rh * 2 + 0], zi1 = d[mt][0 + t1][rh * 2 + 1];
                float zf0 = d[mt][2 + t1][rh * 2 + 0], zf1 = d[mt][2 + t1][rh * 2 + 1];
                float zc0 = d[mt][4 + t1][rh * 2 + 0], zc1 = d[mt][4 + t1][rh * 2 + 1];
                float zo0 = d[mt][6 + t1][rh * 2 + 0], zo1 = d[mt][6 + t1][rh * 2 + 1];

                float2 co = make_float2(0.f, 0.f);
                if (!FIRST) co = *(const float2*)&g_c[pix + f0];

                float ig0 = hsig(zi0 + bias[f0]);
                float fg0 = hsig(zf0 + bias[64 + f0]);
                float zz0 =      zc0 + bias[128 + f0];
                float og0 = hsig(zo0 + bias[192 + f0]);
                float cn0 = fg0 * co.x + ig0 * fmaxf(zz0, 0.f);
                float hn0 = og0 * fmaxf(cn0, 0.f);

                float ig1 = hsig(zi1 + bias[f0 + 1]);
                float fg1 = hsig(zf1 + bias[65 + f0]);
                float zz1 =      zc1 + bias[129 + f0];
                float og1 = hsig(zo1 + bias[193 + f0]);
                float cn1 = fg1 * co.y + ig1 * fmaxf(zz1, 0.f);
                float hn1 = og1 * fmaxf(cn1, 0.f);

                if (!last) {
                    *(float2*)&g_c[pix + f0] = make_float2(cn0, cn1);
                    *(__half2*)&hhout[pix + f0] = __floats2half2_rn(hn0, hn1);
                } else {
                    *(float2*)&out[pix + f0] = make_float2(hn0, hn1);
                }
            }
        }
    }
}

extern "C" void kernel_launch(void* const* d_in, const int* in_sizes, int n_in,
                              void* d_out, int out_size)
{
    const float* x = nullptr; const float* Wt = nullptr;
    const float* Ut = nullptr; const float* bias = nullptr;
    for (int i = 0; i < n_in; ++i) {
        switch (in_sizes[i]) {
            case B_*T_*H_*W_*CIN: x    = (const float*)d_in[i]; break;
            case 3*3*CIN*NC:      Wt   = (const float*)d_in[i]; break;
            case 3*3*F_*NC:       Ut   = (const float*)d_in[i]; break;
            case NC:              bias = (const float*)d_in[i]; break;
        }
    }
    if (!x || !Wt || !Ut || !bias) {
        x = (const float*)d_in[0]; Wt = (const float*)d_in[1];
        Ut = (const float*)d_in[2]; bias = (const float*)d_in[3];
    }
    float* out = (float*)d_out;

    prep_x<<<(B_ * T_ * H_ * W_ * CIN) / 1024, 256>>>(x);
    prep_bf<<<dim3(NSL, 4), 256>>>(Wt, Ut);

    dim3 grid(W_ / 8, H_ / 8, B_);    // 512 CTAs
    dim3 block(256);

    step_mma<true><<<grid, block>>>(bias, 0, 0, out, 0);
    for (int t = 1; t < T_; ++t) {
        int last = (t == T_ - 1);
        step_mma<false><<<grid, block>>>(bias, t, t & 1, out, last);
    }
}